// round 12
// baseline (speedup 1.0000x reference)
#include <cuda_runtime.h>
#include <cuda_bf16.h>
#include <cuda_fp16.h>
#include <cstdint>

// Problem dims (fixed by the dataset)
#define M_TOK 4096            // B*S
#define HDIM  4096
#define IDIM  14336

// ---------------------------------------------------------------------------
// Device scratch (allocation-free rule: __device__ globals)
// ---------------------------------------------------------------------------
__device__ __nv_bfloat16 g_xq[(size_t)M_TOK * HDIM];      // quantized x (ints in bf16)
__device__ float         g_xscale[M_TOK];
__device__ float         g_inter[(size_t)M_TOK * IDIM];   // silu(gate)*up, fp32
__device__ __half        g_q2h[(size_t)M_TOK * IDIM];     // quantized inter (ints in fp16)
__device__ float         g_s2[M_TOK];
__device__ __nv_bfloat16 g_wg_hi[(size_t)IDIM * HDIM];
__device__ __nv_bfloat16 g_wg_lo[(size_t)IDIM * HDIM];
__device__ __nv_bfloat16 g_wu_hi[(size_t)IDIM * HDIM];
__device__ __nv_bfloat16 g_wu_lo[(size_t)IDIM * HDIM];
__device__ __half        g_wd_h [(size_t)HDIM * IDIM];    // down weights, fp16 single

// ---------------------------------------------------------------------------
// PTX helpers (all legal at compute_103 base target)
// ---------------------------------------------------------------------------
__device__ __forceinline__ uint32_t smem_u32(const void* p) {
    uint32_t a;
    asm("{ .reg .u64 t; cvta.to.shared.u64 t, %1; cvt.u32.u64 %0, t; }" : "=r"(a) : "l"(p));
    return a;
}
__device__ __forceinline__ void cp_async16(uint32_t saddr, const void* g) {
    asm volatile("cp.async.cg.shared.global [%0], [%1], 16;\n" :: "r"(saddr), "l"(g));
}
__device__ __forceinline__ void cp_commit() { asm volatile("cp.async.commit_group;\n"); }
template<int N> __device__ __forceinline__ void cp_wait() {
    asm volatile("cp.async.wait_group %0;\n" :: "n"(N));
}
__device__ __forceinline__ void ldsm_x4(uint32_t* r, uint32_t addr) {
    asm volatile("ldmatrix.sync.aligned.m8n8.x4.shared.b16 {%0,%1,%2,%3}, [%4];"
                 : "=r"(r[0]), "=r"(r[1]), "=r"(r[2]), "=r"(r[3]) : "r"(addr));
}
template<bool FP16_T>
__device__ __forceinline__ void mma16816(float* c, const uint32_t* a, uint32_t b0, uint32_t b1) {
    if (FP16_T) {
        asm volatile(
            "mma.sync.aligned.m16n8k16.row.col.f32.f16.f16.f32 "
            "{%0,%1,%2,%3},{%4,%5,%6,%7},{%8,%9},{%0,%1,%2,%3};\n"
            : "+f"(c[0]), "+f"(c[1]), "+f"(c[2]), "+f"(c[3])
            : "r"(a[0]), "r"(a[1]), "r"(a[2]), "r"(a[3]), "r"(b0), "r"(b1));
    } else {
        asm volatile(
            "mma.sync.aligned.m16n8k16.row.col.f32.bf16.bf16.f32 "
            "{%0,%1,%2,%3},{%4,%5,%6,%7},{%8,%9},{%0,%1,%2,%3};\n"
            : "+f"(c[0]), "+f"(c[1]), "+f"(c[2]), "+f"(c[3])
            : "r"(a[0]), "r"(a[1]), "r"(a[2]), "r"(a[3]), "r"(b0), "r"(b1));
    }
}

// ---------------------------------------------------------------------------
// Fused gate/up GEMM + SwiGLU, 512 threads, 16 warps (4m x 4n), warp 32x32.
// Block tile 128x128x64. 4 B matrices (Ghi,Glo,Uhi,Ul o) share the A tile.
// inter = silu(xs*gate) * (xs*up), fp32 out.
// ---------------------------------------------------------------------------
__global__ void __launch_bounds__(512, 1)
fused_gateup_kernel(const uint16_t* __restrict__ A,
                    const uint16_t* __restrict__ Gh,
                    const uint16_t* __restrict__ Gl,
                    const uint16_t* __restrict__ Uh,
                    const uint16_t* __restrict__ Ul,
                    const float* __restrict__ rowscale,
                    float* __restrict__ Cout,
                    int K, int N)
{
    constexpr int TILE  = 16384;       // 128 rows * 128B
    constexpr int STAGE = 5 * TILE;    // A + 4 B tiles = 80KB

    extern __shared__ char smem_raw[];
    const uint32_t sb = (smem_u32(smem_raw) + 127u) & ~127u;

    const int tid  = threadIdx.x;
    const int warp = tid >> 5;
    const int lane = tid & 31;
    const int wm = warp & 3;          // 4 warps over M
    const int wn = warp >> 2;         // 4 warps over N
    const int bm = blockIdx.x * 128;
    const int bn = blockIdx.y * 128;

    const uint16_t* Bs[4] = {Gh, Gl, Uh, Ul};

    float acc[2][2][4][4];            // [gate/up][mi][ni][frag]
    #pragma unroll
    for (int q = 0; q < 2; q++)
        #pragma unroll
        for (int a = 0; a < 2; a++)
            #pragma unroll
            for (int b = 0; b < 4; b++)
                #pragma unroll
                for (int c = 0; c < 4; c++) acc[q][a][b][c] = 0.f;

    const int KT = K >> 6;   // BK=64

    // loader: 5 tiles x 1024 16B-chunks, 512 threads -> 2 chunks per tile
    auto load_stage = [&](int kt, int s) {
        const int k0 = kt * 64;
        #pragma unroll
        for (int i = 0; i < 2; i++) {
            const int id  = tid + i * 512;      // 0..1023
            const int row = id >> 3, c = id & 7;
            const uint32_t doff = (uint32_t)(row * 128 + (((c ^ (row & 7)) << 4)));
            const uint32_t st = sb + s * STAGE + doff;
            cp_async16(st, A + (size_t)(bm + row) * K + k0 + c * 8);
            #pragma unroll
            for (int m = 0; m < 4; m++)
                cp_async16(st + (1 + m) * TILE,
                           Bs[m] + (size_t)(bn + row) * K + k0 + c * 8);
        }
    };

    const int la7 = lane & 7;
    uint32_t a_row[2], b_row[2];
    #pragma unroll
    for (int mi = 0; mi < 2; mi++)
        a_row[mi] = (uint32_t)(wm * 32 + mi * 16 + la7 + ((lane >> 3) & 1) * 8) * 128;
    #pragma unroll
    for (int p = 0; p < 2; p++)
        b_row[p] = (uint32_t)(wn * 32 + p * 16 + la7 + (lane >> 4) * 8) * 128;
    const int kca = (lane >> 4);
    const int kcb = ((lane >> 3) & 1);

    load_stage(0, 0);
    cp_commit();

    for (int kt = 0; kt < KT; kt++) {
        cp_wait<0>();
        __syncthreads();
        if (kt + 1 < KT) load_stage(kt + 1, (kt + 1) & 1);
        cp_commit();

        const uint32_t base = sb + (kt & 1) * STAGE;
        #pragma unroll
        for (int kk = 0; kk < 4; kk++) {
            const uint32_t offa = (uint32_t)(((kk * 2 + kca) ^ la7) << 4);
            const uint32_t offb = (uint32_t)(((kk * 2 + kcb) ^ la7) << 4);
            uint32_t afr[2][4];
            ldsm_x4(afr[0], base + a_row[0] + offa);
            ldsm_x4(afr[1], base + a_row[1] + offa);
            #pragma unroll
            for (int p = 0; p < 2; p++) {
                const uint32_t boff = b_row[p] + offb;
                // order {Ghi, Uhi, Glo, Ulo}: same-accumulator pairs spaced 8 MMAs
                constexpr int remap[4] = {0, 2, 1, 3};
                #pragma unroll
                for (int mm = 0; mm < 4; mm++) {
                    const int m = remap[mm];
                    const int q = m >> 1;
                    uint32_t bfr[4];
                    ldsm_x4(bfr, base + (1 + m) * TILE + boff);
                    mma16816<false>(acc[q][0][2 * p],     afr[0], bfr[0], bfr[1]);
                    mma16816<false>(acc[q][1][2 * p],     afr[1], bfr[0], bfr[1]);
                    mma16816<false>(acc[q][0][2 * p + 1], afr[0], bfr[2], bfr[3]);
                    mma16816<false>(acc[q][1][2 * p + 1], afr[1], bfr[2], bfr[3]);
                }
            }
        }
    }

    // epilogue: inter = silu(xs*gate) * (xs*up)
    #pragma unroll
    for (int mi = 0; mi < 2; mi++) {
        const int r0 = bm + wm * 32 + mi * 16 + (lane >> 2);
        const float s0 = rowscale[r0];
        const float s1 = rowscale[r0 + 8];
        #pragma unroll
        for (int ni = 0; ni < 4; ni++) {
            const int col = bn + wn * 32 + ni * 8 + (lane & 3) * 2;
            float g0 = acc[0][mi][ni][0] * s0, g1 = acc[0][mi][ni][1] * s0;
            float u0 = acc[1][mi][ni][0] * s0, u1 = acc[1][mi][ni][1] * s0;
            float v0 = __fdividef(g0, 1.f + expf(-g0)) * u0;
            float v1 = __fdividef(g1, 1.f + expf(-g1)) * u1;
            *(float2*)&Cout[(size_t)r0 * N + col] = make_float2(v0, v1);
            float g2 = acc[0][mi][ni][2] * s1, g3 = acc[0][mi][ni][3] * s1;
            float u2 = acc[1][mi][ni][2] * s1, u3 = acc[1][mi][ni][3] * s1;
            float v2 = __fdividef(g2, 1.f + expf(-g2)) * u2;
            float v3 = __fdividef(g3, 1.f + expf(-g3)) * u3;
            *(float2*)&Cout[(size_t)(r0 + 8) * N + col] = make_float2(v2, v3);
        }
    }
}

// ---------------------------------------------------------------------------
// Down GEMM (fp16 single), 256 threads, 8 warps (4m x 2n), warp 32x64,
// BM=128 BN=128 BK=64, double-buffered; C = rowscale * acc.
// FIXED vs R11: epilogue indexes acc[mi][ni] (mi=1 rows were dropped before).
// ---------------------------------------------------------------------------
__global__ void __launch_bounds__(256, 2)
down_gemm_kernel(const uint16_t* __restrict__ A,
                 const uint16_t* __restrict__ B0,
                 const float* __restrict__ rowscale,
                 float* __restrict__ Cout,
                 int K, int N)
{
    constexpr int TILE  = 16384;
    constexpr int STAGE = 2 * TILE;

    extern __shared__ char smem_raw[];
    const uint32_t sb = (smem_u32(smem_raw) + 127u) & ~127u;

    const int tid  = threadIdx.x;
    const int warp = tid >> 5;
    const int lane = tid & 31;
    const int wm = warp & 3;
    const int wn = warp >> 2;
    const int bm = blockIdx.x * 128;
    const int bn = blockIdx.y * 128;

    float acc[2][8][4];
    #pragma unroll
    for (int a = 0; a < 2; a++)
        #pragma unroll
        for (int b = 0; b < 8; b++)
            #pragma unroll
            for (int c = 0; c < 4; c++) acc[a][b][c] = 0.f;

    const int KT = K >> 6;

    auto load_stage = [&](int kt, int s) {
        const int k0 = kt * 64;
        #pragma unroll
        for (int i = 0; i < 4; i++) {
            int id  = tid + i * 256;
            int row = id >> 3, c = id & 7;
            uint32_t doff = (uint32_t)(row * 128 + (((c ^ (row & 7)) << 4)));
            cp_async16(sb + s * STAGE + doff, A  + (size_t)(bm + row) * K + k0 + c * 8);
            cp_async16(sb + s * STAGE + TILE + doff, B0 + (size_t)(bn + row) * K + k0 + c * 8);
        }
    };

    const int la7 = lane & 7;
    uint32_t a_row[2], b_row[4];
    #pragma unroll
    for (int mi = 0; mi < 2; mi++)
        a_row[mi] = (uint32_t)(wm * 32 + mi * 16 + la7 + ((lane >> 3) & 1) * 8) * 128;
    #pragma unroll
    for (int p = 0; p < 4; p++)
        b_row[p] = (uint32_t)(wn * 64 + p * 16 + la7 + (lane >> 4) * 8) * 128;
    const int kca = (lane >> 4);
    const int kcb = ((lane >> 3) & 1);

    load_stage(0, 0);
    cp_commit();

    for (int kt = 0; kt < KT; kt++) {
        cp_wait<0>();
        __syncthreads();
        if (kt + 1 < KT) load_stage(kt + 1, (kt + 1) & 1);
        cp_commit();

        const uint32_t base = sb + (kt & 1) * STAGE;
        #pragma unroll
        for (int kk = 0; kk < 4; kk++) {
            const uint32_t offa = (uint32_t)(((kk * 2 + kca) ^ la7) << 4);
            const uint32_t offb = (uint32_t)(((kk * 2 + kcb) ^ la7) << 4);
            uint32_t afr[2][4];
            ldsm_x4(afr[0], base + a_row[0] + offa);
            ldsm_x4(afr[1], base + a_row[1] + offa);
            #pragma unroll
            for (int p = 0; p < 4; p++) {
                uint32_t bfr[4];
                ldsm_x4(bfr, base + TILE + b_row[p] + offb);
                mma16816<true>(acc[0][2 * p],     afr[0], bfr[0], bfr[1]);
                mma16816<true>(acc[1][2 * p],     afr[1], bfr[0], bfr[1]);
                mma16816<true>(acc[0][2 * p + 1], afr[0], bfr[2], bfr[3]);
                mma16816<true>(acc[1][2 * p + 1], afr[1], bfr[2], bfr[3]);
            }
        }
    }

    #pragma unroll
    for (int mi = 0; mi < 2; mi++) {
        const int r0 = bm + wm * 32 + mi * 16 + (lane >> 2);
        const float s0 = rowscale[r0];
        const float s1 = rowscale[r0 + 8];
        #pragma unroll
        for (int ni = 0; ni < 8; ni++) {
            const int col = bn + wn * 64 + ni * 8 + (lane & 3) * 2;
            *(float2*)&Cout[(size_t)r0 * N + col] =
                make_float2(acc[mi][ni][0] * s0, acc[mi][ni][1] * s0);
            *(float2*)&Cout[(size_t)(r0 + 8) * N + col] =
                make_float2(acc[mi][ni][2] * s1, acc[mi][ni][3] * s1);
        }
    }
}

// ---------------------------------------------------------------------------
// Weight split fp32 -> bf16 hi/lo (vectorized)
// ---------------------------------------------------------------------------
__global__ void split_one_kernel(const float4* __restrict__ src,
                                 __nv_bfloat162* __restrict__ hi,
                                 __nv_bfloat162* __restrict__ lo, int n4) {
    const int stride = gridDim.x * blockDim.x;
    for (int i = blockIdx.x * blockDim.x + threadIdx.x; i < n4; i += stride) {
        float4 w = src[i];
        __nv_bfloat16 hx = __float2bfloat16_rn(w.x);
        __nv_bfloat16 hy = __float2bfloat16_rn(w.y);
        __nv_bfloat16 hz = __float2bfloat16_rn(w.z);
        __nv_bfloat16 hw = __float2bfloat16_rn(w.w);
        hi[2*i]   = __halves2bfloat162(hx, hy);
        hi[2*i+1] = __halves2bfloat162(hz, hw);
        lo[2*i]   = __halves2bfloat162(__float2bfloat16_rn(w.x - __bfloat162float(hx)),
                                       __float2bfloat16_rn(w.y - __bfloat162float(hy)));
        lo[2*i+1] = __halves2bfloat162(__float2bfloat16_rn(w.z - __bfloat162float(hz)),
                                       __float2bfloat16_rn(w.w - __bfloat162float(hw)));
    }
}

// ---------------------------------------------------------------------------
// fp32 -> fp16 convert (down weights)
// ---------------------------------------------------------------------------
__global__ void conv_half_kernel(const float4* __restrict__ src,
                                 __half2* __restrict__ dst, int n4) {
    const int stride = gridDim.x * blockDim.x;
    for (int i = blockIdx.x * blockDim.x + threadIdx.x; i < n4; i += stride) {
        float4 w = src[i];
        dst[2*i]   = __floats2half2_rn(w.x, w.y);
        dst[2*i+1] = __floats2half2_rn(w.z, w.w);
    }
}

// ---------------------------------------------------------------------------
// Block max-reduce
// ---------------------------------------------------------------------------
__device__ __forceinline__ float block_max(float v, float* red) {
    #pragma unroll
    for (int o = 16; o; o >>= 1) v = fmaxf(v, __shfl_xor_sync(0xFFFFFFFFu, v, o));
    if ((threadIdx.x & 31) == 0) red[threadIdx.x >> 5] = v;
    __syncthreads();
    if (threadIdx.x < 32) {
        float w = (threadIdx.x < (blockDim.x >> 5)) ? red[threadIdx.x] : 0.f;
        #pragma unroll
        for (int o = 16; o; o >>= 1) w = fmaxf(w, __shfl_xor_sync(0xFFFFFFFFu, w, o));
        if (threadIdx.x == 0) red[0] = w;
    }
    __syncthreads();
    return red[0];
}

// ---------------------------------------------------------------------------
// Per-token fake-quant of x -> bf16 ints (row cached in smem)
// ---------------------------------------------------------------------------
__global__ void quant_x_kernel(const float* __restrict__ x) {
    __shared__ float red[32];
    __shared__ float row[HDIM];
    const int t = blockIdx.x;
    const float4* xr = (const float4*)(x + (size_t)t * HDIM);
    float amax = 0.f;
    for (int i = threadIdx.x; i < HDIM / 4; i += blockDim.x) {
        float4 v = xr[i];
        ((float4*)row)[i] = v;
        amax = fmaxf(amax, fmaxf(fmaxf(fabsf(v.x), fabsf(v.y)), fmaxf(fabsf(v.z), fabsf(v.w))));
    }
    __syncthreads();
    amax = block_max(amax, red);
    const float scale = fmaxf(amax * (1.0f / 127.0f), 1e-8f);
    if (threadIdx.x == 0) g_xscale[t] = scale;
    const float inv = 1.0f / scale;
    for (int i = threadIdx.x; i < HDIM; i += blockDim.x) {
        float q = rintf(row[i] * inv);
        q = fminf(fmaxf(q, -128.f), 127.f);
        g_xq[(size_t)t * HDIM + i] = __float2bfloat16_rn(q);
    }
}

// ---------------------------------------------------------------------------
// Per-token fake-quant of inter -> fp16 ints
// ---------------------------------------------------------------------------
__global__ void quant2_kernel() {
    extern __shared__ float srow[];    // IDIM floats
    __shared__ float red[32];
    const int t = blockIdx.x;
    const float4* ir = (const float4*)(g_inter + (size_t)t * IDIM);
    float amax = 0.f;
    for (int i = threadIdx.x; i < IDIM / 4; i += blockDim.x) {
        float4 v = ir[i];
        ((float4*)srow)[i] = v;
        amax = fmaxf(amax, fmaxf(fmaxf(fabsf(v.x), fabsf(v.y)), fmaxf(fabsf(v.z), fabsf(v.w))));
    }
    __syncthreads();
    amax = block_max(amax, red);
    const float scale = fmaxf(amax * (1.0f / 127.0f), 1e-8f);
    if (threadIdx.x == 0) g_s2[t] = scale;
    const float inv = 1.0f / scale;
    for (int i = threadIdx.x; i < IDIM; i += blockDim.x) {
        float q = rintf(srow[i] * inv);
        q = fminf(fmaxf(q, -128.f), 127.f);
        g_q2h[(size_t)t * IDIM + i] = __float2half_rn(q);
    }
}

// ---------------------------------------------------------------------------
// Host launcher
// ---------------------------------------------------------------------------
extern "C" void kernel_launch(void* const* d_in, const int* in_sizes, int n_in,
                              void* d_out, int out_size) {
    const float* x  = (const float*)d_in[0];
    const float* wg = (const float*)d_in[1];
    const float* wu = (const float*)d_in[2];
    const float* wd = (const float*)d_in[3];
    float* out = (float*)d_out;
    (void)in_sizes; (void)n_in; (void)out_size;

    void *p_xq, *p_xs, *p_inter, *p_q2, *p_s2;
    void *p_wgh, *p_wgl, *p_wuh, *p_wul, *p_wdh;
    cudaGetSymbolAddress(&p_xq, g_xq);      cudaGetSymbolAddress(&p_xs, g_xscale);
    cudaGetSymbolAddress(&p_inter, g_inter);
    cudaGetSymbolAddress(&p_q2, g_q2h);     cudaGetSymbolAddress(&p_s2, g_s2);
    cudaGetSymbolAddress(&p_wgh, g_wg_hi);  cudaGetSymbolAddress(&p_wgl, g_wg_lo);
    cudaGetSymbolAddress(&p_wuh, g_wu_hi);  cudaGetSymbolAddress(&p_wul, g_wu_lo);
    cudaGetSymbolAddress(&p_wdh, g_wd_h);

    const int smem_fused = 2 * 5 * 16384 + 128;   // 163968
    const int smem_down  = 2 * 2 * 16384 + 128;   // 65664
    const int smem_q2    = IDIM * (int)sizeof(float);
    cudaFuncSetAttribute(fused_gateup_kernel,
                         cudaFuncAttributeMaxDynamicSharedMemorySize, smem_fused);
    cudaFuncSetAttribute(down_gemm_kernel,
                         cudaFuncAttributeMaxDynamicSharedMemorySize, smem_down);
    cudaFuncSetAttribute(quant2_kernel,
                         cudaFuncAttributeMaxDynamicSharedMemorySize, smem_q2);

    // 1) gate/up weights -> bf16 hi/lo; down weights -> fp16
    const int n4 = (IDIM / 4) * HDIM;
    split_one_kernel<<<1024, 256>>>((const float4*)wg, (__nv_bfloat162*)p_wgh,
                                    (__nv_bfloat162*)p_wgl, n4);
    split_one_kernel<<<1024, 256>>>((const float4*)wu, (__nv_bfloat162*)p_wuh,
                                    (__nv_bfloat162*)p_wul, n4);
    conv_half_kernel<<<1024, 256>>>((const float4*)wd, (__half2*)p_wdh, n4);

    // 2) per-token fake-quant of x
    quant_x_kernel<<<M_TOK, 256>>>(x);

    // 3) fused gate/up GEMM (bf16 hi+lo) + SwiGLU epilogue -> inter
    dim3 g1(M_TOK / 128, IDIM / 128);   // (32, 112), m fastest
    fused_gateup_kernel<<<g1, 512, smem_fused>>>(
        (const uint16_t*)p_xq,
        (const uint16_t*)p_wgh, (const uint16_t*)p_wgl,
        (const uint16_t*)p_wuh, (const uint16_t*)p_wul,
        (const float*)p_xs, (float*)p_inter, HDIM, IDIM);

    // 4) fake-quant of inter -> fp16 ints
    quant2_kernel<<<M_TOK, 512, smem_q2>>>();

    // 5) down GEMM (fp16 single) -> out
    dim3 g3(M_TOK / 128, HDIM / 128);   // (32, 32)
    down_gemm_kernel<<<g3, 256, smem_down>>>(
        (const uint16_t*)p_q2, (const uint16_t*)p_wdh,
        (const float*)p_s2, out, IDIM, HDIM);
}

// round 13
// speedup vs baseline: 1.0119x; 1.0119x over previous
#include <cuda_runtime.h>
#include <cuda_bf16.h>
#include <cuda_fp16.h>
#include <cstdint>

// Problem dims (fixed by the dataset)
#define M_TOK 4096            // B*S
#define HDIM  4096
#define IDIM  14336

// ---------------------------------------------------------------------------
// Device scratch (allocation-free rule: __device__ globals)
// ---------------------------------------------------------------------------
__device__ __nv_bfloat16 g_xq[(size_t)M_TOK * HDIM];      // quantized x (ints in bf16)
__device__ float         g_xscale[M_TOK];
__device__ float         g_inter[(size_t)M_TOK * IDIM];   // silu(gate)*up, fp32
__device__ __half        g_q2h[(size_t)M_TOK * IDIM];     // quantized inter (ints in fp16)
__device__ float         g_s2[M_TOK];
__device__ __nv_bfloat16 g_wg_hi[(size_t)IDIM * HDIM];
__device__ __nv_bfloat16 g_wg_lo[(size_t)IDIM * HDIM];
__device__ __nv_bfloat16 g_wu_hi[(size_t)IDIM * HDIM];
__device__ __nv_bfloat16 g_wu_lo[(size_t)IDIM * HDIM];
__device__ __half        g_wd_h [(size_t)HDIM * IDIM];    // down weights, fp16 single

// ---------------------------------------------------------------------------
// PTX helpers (all legal at compute_103 base target)
// ---------------------------------------------------------------------------
__device__ __forceinline__ uint32_t smem_u32(const void* p) {
    uint32_t a;
    asm("{ .reg .u64 t; cvta.to.shared.u64 t, %1; cvt.u32.u64 %0, t; }" : "=r"(a) : "l"(p));
    return a;
}
__device__ __forceinline__ void cp_async16(uint32_t saddr, const void* g) {
    asm volatile("cp.async.cg.shared.global [%0], [%1], 16;\n" :: "r"(saddr), "l"(g));
}
__device__ __forceinline__ void cp_commit() { asm volatile("cp.async.commit_group;\n"); }
template<int N> __device__ __forceinline__ void cp_wait() {
    asm volatile("cp.async.wait_group %0;\n" :: "n"(N));
}
__device__ __forceinline__ void ldsm_x4(uint32_t* r, uint32_t addr) {
    asm volatile("ldmatrix.sync.aligned.m8n8.x4.shared.b16 {%0,%1,%2,%3}, [%4];"
                 : "=r"(r[0]), "=r"(r[1]), "=r"(r[2]), "=r"(r[3]) : "r"(addr));
}
template<bool FP16_T>
__device__ __forceinline__ void mma16816(float* c, const uint32_t* a, uint32_t b0, uint32_t b1) {
    if (FP16_T) {
        asm volatile(
            "mma.sync.aligned.m16n8k16.row.col.f32.f16.f16.f32 "
            "{%0,%1,%2,%3},{%4,%5,%6,%7},{%8,%9},{%0,%1,%2,%3};\n"
            : "+f"(c[0]), "+f"(c[1]), "+f"(c[2]), "+f"(c[3])
            : "r"(a[0]), "r"(a[1]), "r"(a[2]), "r"(a[3]), "r"(b0), "r"(b1));
    } else {
        asm volatile(
            "mma.sync.aligned.m16n8k16.row.col.f32.bf16.bf16.f32 "
            "{%0,%1,%2,%3},{%4,%5,%6,%7},{%8,%9},{%0,%1,%2,%3};\n"
            : "+f"(c[0]), "+f"(c[1]), "+f"(c[2]), "+f"(c[3])
            : "r"(a[0]), "r"(a[1]), "r"(a[2]), "r"(a[3]), "r"(b0), "r"(b1));
    }
}

// ---------------------------------------------------------------------------
// Fused gate/up GEMM + SwiGLU (R10-proven config): 256 threads, 8 warps
// (4m x 2n), warp 32x64, block tile 128x128x64, double-buffered cp.async.
// 4 B matrices (Ghi,Glo,Uhi,Ulo) share the A tile; hi/lo share accumulators.
// inter = silu(xs*gate) * (xs*up), fp32 out.
// ---------------------------------------------------------------------------
__global__ void __launch_bounds__(256, 1)
fused_gateup_kernel(const uint16_t* __restrict__ A,
                    const uint16_t* __restrict__ Gh,
                    const uint16_t* __restrict__ Gl,
                    const uint16_t* __restrict__ Uh,
                    const uint16_t* __restrict__ Ul,
                    const float* __restrict__ rowscale,
                    float* __restrict__ Cout,
                    int K, int N)
{
    constexpr int TILE  = 16384;       // 128 rows * 128B
    constexpr int STAGE = 5 * TILE;    // A + 4 B tiles = 80KB

    extern __shared__ char smem_raw[];
    const uint32_t sb = (smem_u32(smem_raw) + 127u) & ~127u;

    const int tid  = threadIdx.x;
    const int warp = tid >> 5;
    const int lane = tid & 31;
    const int wm = warp & 3;          // 4 warps over M
    const int wn = warp >> 2;         // 2 warps over N
    const int bm = blockIdx.x * 128;
    const int bn = blockIdx.y * 128;

    const uint16_t* Bs[4] = {Gh, Gl, Uh, Ul};

    float acc[2][2][8][4];            // [gate/up][mi][ni][frag]
    #pragma unroll
    for (int q = 0; q < 2; q++)
        #pragma unroll
        for (int a = 0; a < 2; a++)
            #pragma unroll
            for (int b = 0; b < 8; b++)
                #pragma unroll
                for (int c = 0; c < 4; c++) acc[q][a][b][c] = 0.f;

    const int KT = K >> 6;   // BK=64

    // per-stage loader: 5 tiles x 1024 16B chunks, 256 threads -> 4 per tile
    auto load_stage = [&](int kt, int s) {
        const int k0 = kt * 64;
        #pragma unroll
        for (int i = 0; i < 4; i++) {
            int id  = tid + i * 256;       // 0..1023
            int row = id >> 3, c = id & 7;
            uint32_t dst = sb + s * STAGE + row * 128 + (((c ^ (row & 7)) << 4));
            cp_async16(dst, A + (size_t)(bm + row) * K + k0 + c * 8);
        }
        #pragma unroll
        for (int m = 0; m < 4; m++) {
            #pragma unroll
            for (int i = 0; i < 4; i++) {
                int id  = tid + i * 256;
                int row = id >> 3, c = id & 7;
                uint32_t dst = sb + s * STAGE + (1 + m) * TILE + row * 128
                             + (((c ^ (row & 7)) << 4));
                cp_async16(dst, Bs[m] + (size_t)(bn + row) * K + k0 + c * 8);
            }
        }
    };

    const int la7 = lane & 7;
    uint32_t a_row[2], b_row[4];
    #pragma unroll
    for (int mi = 0; mi < 2; mi++)
        a_row[mi] = (uint32_t)(wm * 32 + mi * 16 + la7 + ((lane >> 3) & 1) * 8) * 128;
    #pragma unroll
    for (int p = 0; p < 4; p++)
        b_row[p] = (uint32_t)(wn * 64 + p * 16 + la7 + (lane >> 4) * 8) * 128;
    const int kca = (lane >> 4);
    const int kcb = ((lane >> 3) & 1);

    load_stage(0, 0);
    cp_commit();

    for (int kt = 0; kt < KT; kt++) {
        cp_wait<0>();
        __syncthreads();
        if (kt + 1 < KT) load_stage(kt + 1, (kt + 1) & 1);
        cp_commit();

        const uint32_t base = sb + (kt & 1) * STAGE;
        #pragma unroll
        for (int kk = 0; kk < 4; kk++) {
            const uint32_t offa = (uint32_t)(((kk * 2 + kca) ^ la7) << 4);
            const uint32_t offb = (uint32_t)(((kk * 2 + kcb) ^ la7) << 4);
            uint32_t afr[2][4];
            ldsm_x4(afr[0], base + a_row[0] + offa);
            ldsm_x4(afr[1], base + a_row[1] + offa);
            #pragma unroll
            for (int p = 0; p < 4; p++) {
                #pragma unroll
                for (int m = 0; m < 4; m++) {
                    uint32_t bfr[4];
                    ldsm_x4(bfr, base + (1 + m) * TILE + b_row[p] + offb);
                    float* c0 = acc[m >> 1][0][2 * p];
                    float* c1 = acc[m >> 1][1][2 * p];
                    float* c2 = acc[m >> 1][0][2 * p + 1];
                    float* c3 = acc[m >> 1][1][2 * p + 1];
                    mma16816<false>(c0, afr[0], bfr[0], bfr[1]);
                    mma16816<false>(c1, afr[1], bfr[0], bfr[1]);
                    mma16816<false>(c2, afr[0], bfr[2], bfr[3]);
                    mma16816<false>(c3, afr[1], bfr[2], bfr[3]);
                }
            }
        }
    }

    // epilogue: inter = silu(xs*gate) * (xs*up)
    #pragma unroll
    for (int mi = 0; mi < 2; mi++) {
        const int r0 = bm + wm * 32 + mi * 16 + (lane >> 2);
        const float s0 = rowscale[r0];
        const float s1 = rowscale[r0 + 8];
        #pragma unroll
        for (int ni = 0; ni < 8; ni++) {
            const int col = bn + wn * 64 + ni * 8 + (lane & 3) * 2;
            float g0 = acc[0][mi][ni][0] * s0, g1 = acc[0][mi][ni][1] * s0;
            float u0 = acc[1][mi][ni][0] * s0, u1 = acc[1][mi][ni][1] * s0;
            float v0 = __fdividef(g0, 1.f + expf(-g0)) * u0;
            float v1 = __fdividef(g1, 1.f + expf(-g1)) * u1;
            *(float2*)&Cout[(size_t)r0 * N + col] = make_float2(v0, v1);
            float g2 = acc[0][mi][ni][2] * s1, g3 = acc[0][mi][ni][3] * s1;
            float u2 = acc[1][mi][ni][2] * s1, u3 = acc[1][mi][ni][3] * s1;
            float v2 = __fdividef(g2, 1.f + expf(-g2)) * u2;
            float v3 = __fdividef(g3, 1.f + expf(-g3)) * u3;
            *(float2*)&Cout[(size_t)(r0 + 8) * N + col] = make_float2(v2, v3);
        }
    }
}

// ---------------------------------------------------------------------------
// Down GEMM (fp16 single), 256 threads, 8 warps (4m x 2n), warp 32x64,
// BM=128 BN=128 BK=64. NEW: 3-stage cp.async ring (wait_group 1) so two
// stages stay in flight during compute; 96KB smem, 2 CTAs/SM.
// ---------------------------------------------------------------------------
__global__ void __launch_bounds__(256, 2)
down_gemm_kernel(const uint16_t* __restrict__ A,
                 const uint16_t* __restrict__ B0,
                 const float* __restrict__ rowscale,
                 float* __restrict__ Cout,
                 int K, int N)
{
    constexpr int TILE  = 16384;
    constexpr int STAGE = 2 * TILE;     // A + B = 32KB
    constexpr int NSTG  = 3;

    extern __shared__ char smem_raw[];
    const uint32_t sb = (smem_u32(smem_raw) + 127u) & ~127u;

    const int tid  = threadIdx.x;
    const int warp = tid >> 5;
    const int lane = tid & 31;
    const int wm = warp & 3;
    const int wn = warp >> 2;
    const int bm = blockIdx.x * 128;
    const int bn = blockIdx.y * 128;

    float acc[2][8][4];
    #pragma unroll
    for (int a = 0; a < 2; a++)
        #pragma unroll
        for (int b = 0; b < 8; b++)
            #pragma unroll
            for (int c = 0; c < 4; c++) acc[a][b][c] = 0.f;

    const int KT = K >> 6;

    auto load_stage = [&](int kt, int s) {
        const int k0 = kt * 64;
        #pragma unroll
        for (int i = 0; i < 4; i++) {
            int id  = tid + i * 256;
            int row = id >> 3, c = id & 7;
            uint32_t doff = (uint32_t)(row * 128 + (((c ^ (row & 7)) << 4)));
            cp_async16(sb + s * STAGE + doff,        A  + (size_t)(bm + row) * K + k0 + c * 8);
            cp_async16(sb + s * STAGE + TILE + doff, B0 + (size_t)(bn + row) * K + k0 + c * 8);
        }
    };

    const int la7 = lane & 7;
    uint32_t a_row[2], b_row[4];
    #pragma unroll
    for (int mi = 0; mi < 2; mi++)
        a_row[mi] = (uint32_t)(wm * 32 + mi * 16 + la7 + ((lane >> 3) & 1) * 8) * 128;
    #pragma unroll
    for (int p = 0; p < 4; p++)
        b_row[p] = (uint32_t)(wn * 64 + p * 16 + la7 + (lane >> 4) * 8) * 128;
    const int kca = (lane >> 4);
    const int kcb = ((lane >> 3) & 1);

    load_stage(0, 0); cp_commit();
    load_stage(1, 1); cp_commit();

    for (int kt = 0; kt < KT; kt++) {
        cp_wait<1>();                 // stage kt complete; kt+1 may be in flight
        __syncthreads();
        if (kt + 2 < KT) load_stage(kt + 2, (kt + 2) % NSTG);
        cp_commit();

        const uint32_t base = sb + (kt % NSTG) * STAGE;
        #pragma unroll
        for (int kk = 0; kk < 4; kk++) {
            const uint32_t offa = (uint32_t)(((kk * 2 + kca) ^ la7) << 4);
            const uint32_t offb = (uint32_t)(((kk * 2 + kcb) ^ la7) << 4);
            uint32_t afr[2][4];
            ldsm_x4(afr[0], base + a_row[0] + offa);
            ldsm_x4(afr[1], base + a_row[1] + offa);
            #pragma unroll
            for (int p = 0; p < 4; p++) {
                uint32_t bfr[4];
                ldsm_x4(bfr, base + TILE + b_row[p] + offb);
                mma16816<true>(acc[0][2 * p],     afr[0], bfr[0], bfr[1]);
                mma16816<true>(acc[1][2 * p],     afr[1], bfr[0], bfr[1]);
                mma16816<true>(acc[0][2 * p + 1], afr[0], bfr[2], bfr[3]);
                mma16816<true>(acc[1][2 * p + 1], afr[1], bfr[2], bfr[3]);
            }
        }
    }

    #pragma unroll
    for (int mi = 0; mi < 2; mi++) {
        const int r0 = bm + wm * 32 + mi * 16 + (lane >> 2);
        const float s0 = rowscale[r0];
        const float s1 = rowscale[r0 + 8];
        #pragma unroll
        for (int ni = 0; ni < 8; ni++) {
            const int col = bn + wn * 64 + ni * 8 + (lane & 3) * 2;
            *(float2*)&Cout[(size_t)r0 * N + col] =
                make_float2(acc[mi][ni][0] * s0, acc[mi][ni][1] * s0);
            *(float2*)&Cout[(size_t)(r0 + 8) * N + col] =
                make_float2(acc[mi][ni][2] * s1, acc[mi][ni][3] * s1);
        }
    }
}

// ---------------------------------------------------------------------------
// Weight split fp32 -> bf16 hi/lo (vectorized)
// ---------------------------------------------------------------------------
__global__ void split_one_kernel(const float4* __restrict__ src,
                                 __nv_bfloat162* __restrict__ hi,
                                 __nv_bfloat162* __restrict__ lo, int n4) {
    const int stride = gridDim.x * blockDim.x;
    for (int i = blockIdx.x * blockDim.x + threadIdx.x; i < n4; i += stride) {
        float4 w = src[i];
        __nv_bfloat16 hx = __float2bfloat16_rn(w.x);
        __nv_bfloat16 hy = __float2bfloat16_rn(w.y);
        __nv_bfloat16 hz = __float2bfloat16_rn(w.z);
        __nv_bfloat16 hw = __float2bfloat16_rn(w.w);
        hi[2*i]   = __halves2bfloat162(hx, hy);
        hi[2*i+1] = __halves2bfloat162(hz, hw);
        lo[2*i]   = __halves2bfloat162(__float2bfloat16_rn(w.x - __bfloat162float(hx)),
                                       __float2bfloat16_rn(w.y - __bfloat162float(hy)));
        lo[2*i+1] = __halves2bfloat162(__float2bfloat16_rn(w.z - __bfloat162float(hz)),
                                       __float2bfloat16_rn(w.w - __bfloat162float(hw)));
    }
}

// ---------------------------------------------------------------------------
// fp32 -> fp16 convert (down weights)
// ---------------------------------------------------------------------------
__global__ void conv_half_kernel(const float4* __restrict__ src,
                                 __half2* __restrict__ dst, int n4) {
    const int stride = gridDim.x * blockDim.x;
    for (int i = blockIdx.x * blockDim.x + threadIdx.x; i < n4; i += stride) {
        float4 w = src[i];
        dst[2*i]   = __floats2half2_rn(w.x, w.y);
        dst[2*i+1] = __floats2half2_rn(w.z, w.w);
    }
}

// ---------------------------------------------------------------------------
// Block max-reduce
// ---------------------------------------------------------------------------
__device__ __forceinline__ float block_max(float v, float* red) {
    #pragma unroll
    for (int o = 16; o; o >>= 1) v = fmaxf(v, __shfl_xor_sync(0xFFFFFFFFu, v, o));
    if ((threadIdx.x & 31) == 0) red[threadIdx.x >> 5] = v;
    __syncthreads();
    if (threadIdx.x < 32) {
        float w = (threadIdx.x < (blockDim.x >> 5)) ? red[threadIdx.x] : 0.f;
        #pragma unroll
        for (int o = 16; o; o >>= 1) w = fmaxf(w, __shfl_xor_sync(0xFFFFFFFFu, w, o));
        if (threadIdx.x == 0) red[0] = w;
    }
    __syncthreads();
    return red[0];
}

// ---------------------------------------------------------------------------
// Per-token fake-quant of x -> bf16 ints (row cached in smem)
// ---------------------------------------------------------------------------
__global__ void quant_x_kernel(const float* __restrict__ x) {
    __shared__ float red[32];
    __shared__ float row[HDIM];
    const int t = blockIdx.x;
    const float4* xr = (const float4*)(x + (size_t)t * HDIM);
    float amax = 0.f;
    for (int i = threadIdx.x; i < HDIM / 4; i += blockDim.x) {
        float4 v = xr[i];
        ((float4*)row)[i] = v;
        amax = fmaxf(amax, fmaxf(fmaxf(fabsf(v.x), fabsf(v.y)), fmaxf(fabsf(v.z), fabsf(v.w))));
    }
    __syncthreads();
    amax = block_max(amax, red);
    const float scale = fmaxf(amax * (1.0f / 127.0f), 1e-8f);
    if (threadIdx.x == 0) g_xscale[t] = scale;
    const float inv = 1.0f / scale;
    for (int i = threadIdx.x; i < HDIM; i += blockDim.x) {
        float q = rintf(row[i] * inv);
        q = fminf(fmaxf(q, -128.f), 127.f);
        g_xq[(size_t)t * HDIM + i] = __float2bfloat16_rn(q);
    }
}

// ---------------------------------------------------------------------------
// Per-token fake-quant of inter -> fp16 ints
// ---------------------------------------------------------------------------
__global__ void quant2_kernel() {
    extern __shared__ float srow[];    // IDIM floats
    __shared__ float red[32];
    const int t = blockIdx.x;
    const float4* ir = (const float4*)(g_inter + (size_t)t * IDIM);
    float amax = 0.f;
    for (int i = threadIdx.x; i < IDIM / 4; i += blockDim.x) {
        float4 v = ir[i];
        ((float4*)srow)[i] = v;
        amax = fmaxf(amax, fmaxf(fmaxf(fabsf(v.x), fabsf(v.y)), fmaxf(fabsf(v.z), fabsf(v.w))));
    }
    __syncthreads();
    amax = block_max(amax, red);
    const float scale = fmaxf(amax * (1.0f / 127.0f), 1e-8f);
    if (threadIdx.x == 0) g_s2[t] = scale;
    const float inv = 1.0f / scale;
    for (int i = threadIdx.x; i < IDIM; i += blockDim.x) {
        float q = rintf(srow[i] * inv);
        q = fminf(fmaxf(q, -128.f), 127.f);
        g_q2h[(size_t)t * IDIM + i] = __float2half_rn(q);
    }
}

// ---------------------------------------------------------------------------
// Host launcher
// ---------------------------------------------------------------------------
extern "C" void kernel_launch(void* const* d_in, const int* in_sizes, int n_in,
                              void* d_out, int out_size) {
    const float* x  = (const float*)d_in[0];
    const float* wg = (const float*)d_in[1];
    const float* wu = (const float*)d_in[2];
    const float* wd = (const float*)d_in[3];
    float* out = (float*)d_out;
    (void)in_sizes; (void)n_in; (void)out_size;

    void *p_xq, *p_xs, *p_inter, *p_q2, *p_s2;
    void *p_wgh, *p_wgl, *p_wuh, *p_wul, *p_wdh;
    cudaGetSymbolAddress(&p_xq, g_xq);      cudaGetSymbolAddress(&p_xs, g_xscale);
    cudaGetSymbolAddress(&p_inter, g_inter);
    cudaGetSymbolAddress(&p_q2, g_q2h);     cudaGetSymbolAddress(&p_s2, g_s2);
    cudaGetSymbolAddress(&p_wgh, g_wg_hi);  cudaGetSymbolAddress(&p_wgl, g_wg_lo);
    cudaGetSymbolAddress(&p_wuh, g_wu_hi);  cudaGetSymbolAddress(&p_wul, g_wu_lo);
    cudaGetSymbolAddress(&p_wdh, g_wd_h);

    const int smem_fused = 2 * 5 * 16384 + 128;   // 163968
    const int smem_down  = 3 * 2 * 16384 + 128;   // 98432 (3-stage ring)
    const int smem_q2    = IDIM * (int)sizeof(float);
    cudaFuncSetAttribute(fused_gateup_kernel,
                         cudaFuncAttributeMaxDynamicSharedMemorySize, smem_fused);
    cudaFuncSetAttribute(down_gemm_kernel,
                         cudaFuncAttributeMaxDynamicSharedMemorySize, smem_down);
    cudaFuncSetAttribute(quant2_kernel,
                         cudaFuncAttributeMaxDynamicSharedMemorySize, smem_q2);

    // 1) gate/up weights -> bf16 hi/lo; down weights -> fp16
    const int n4 = (IDIM / 4) * HDIM;
    split_one_kernel<<<1024, 256>>>((const float4*)wg, (__nv_bfloat162*)p_wgh,
                                    (__nv_bfloat162*)p_wgl, n4);
    split_one_kernel<<<1024, 256>>>((const float4*)wu, (__nv_bfloat162*)p_wuh,
                                    (__nv_bfloat162*)p_wul, n4);
    conv_half_kernel<<<1024, 256>>>((const float4*)wd, (__half2*)p_wdh, n4);

    // 2) per-token fake-quant of x
    quant_x_kernel<<<M_TOK, 256>>>(x);

    // 3) fused gate/up GEMM (bf16 hi+lo) + SwiGLU epilogue -> inter
    dim3 g1(M_TOK / 128, IDIM / 128);   // (32, 112), m fastest
    fused_gateup_kernel<<<g1, 256, smem_fused>>>(
        (const uint16_t*)p_xq,
        (const uint16_t*)p_wgh, (const uint16_t*)p_wgl,
        (const uint16_t*)p_wuh, (const uint16_t*)p_wul,
        (const float*)p_xs, (float*)p_inter, HDIM, IDIM);

    // 4) fake-quant of inter -> fp16 ints
    quant2_kernel<<<M_TOK, 512, smem_q2>>>();

    // 5) down GEMM (fp16 single, 3-stage pipeline) -> out
    dim3 g3(M_TOK / 128, HDIM / 128);   // (32, 32)
    down_gemm_kernel<<<g3, 256, smem_down>>>(
        (const uint16_t*)p_q2, (const uint16_t*)p_wdh,
        (const float*)p_s2, out, IDIM, HDIM);
}

// round 16
// speedup vs baseline: 1.0195x; 1.0076x over previous
#include <cuda_runtime.h>
#include <cuda_bf16.h>
#include <cuda_fp16.h>
#include <cstdint>

// Problem dims (fixed by the dataset)
#define M_TOK 4096            // B*S
#define HDIM  4096
#define IDIM  14336

// ---------------------------------------------------------------------------
// Device scratch (allocation-free rule: __device__ globals)
// ---------------------------------------------------------------------------
__device__ __nv_bfloat16 g_xq[(size_t)M_TOK * HDIM];      // quantized x (ints in bf16)
__device__ float         g_xscale[M_TOK];
__device__ float         g_inter[(size_t)M_TOK * IDIM];   // silu(gate)*up, fp32
__device__ __half        g_q2h[(size_t)M_TOK * IDIM];     // quantized inter (ints in fp16)
__device__ float         g_s2[M_TOK];
__device__ __nv_bfloat16 g_wg_hi[(size_t)IDIM * HDIM];
__device__ __nv_bfloat16 g_wg_lo[(size_t)IDIM * HDIM];
__device__ __nv_bfloat16 g_wu_hi[(size_t)IDIM * HDIM];
__device__ __nv_bfloat16 g_wu_lo[(size_t)IDIM * HDIM];
__device__ __half        g_wd_h [(size_t)HDIM * IDIM];    // down weights, fp16 single

// ---------------------------------------------------------------------------
// PTX helpers (all legal at compute_103 base target)
// ---------------------------------------------------------------------------
__device__ __forceinline__ uint32_t smem_u32(const void* p) {
    uint32_t a;
    asm("{ .reg .u64 t; cvta.to.shared.u64 t, %1; cvt.u32.u64 %0, t; }" : "=r"(a) : "l"(p));
    return a;
}
__device__ __forceinline__ void cp_async16(uint32_t saddr, const void* g) {
    asm volatile("cp.async.cg.shared.global [%0], [%1], 16;\n" :: "r"(saddr), "l"(g));
}
__device__ __forceinline__ void cp_commit() { asm volatile("cp.async.commit_group;\n"); }
template<int N> __device__ __forceinline__ void cp_wait() {
    asm volatile("cp.async.wait_group %0;\n" :: "n"(N));
}
__device__ __forceinline__ void ldsm_x4(uint32_t* r, uint32_t addr) {
    asm volatile("ldmatrix.sync.aligned.m8n8.x4.shared.b16 {%0,%1,%2,%3}, [%4];"
                 : "=r"(r[0]), "=r"(r[1]), "=r"(r[2]), "=r"(r[3]) : "r"(addr));
}
template<bool FP16_T>
__device__ __forceinline__ void mma16816(float* c, const uint32_t* a, uint32_t b0, uint32_t b1) {
    if (FP16_T) {
        asm volatile(
            "mma.sync.aligned.m16n8k16.row.col.f32.f16.f16.f32 "
            "{%0,%1,%2,%3},{%4,%5,%6,%7},{%8,%9},{%0,%1,%2,%3};\n"
            : "+f"(c[0]), "+f"(c[1]), "+f"(c[2]), "+f"(c[3])
            : "r"(a[0]), "r"(a[1]), "r"(a[2]), "r"(a[3]), "r"(b0), "r"(b1));
    } else {
        asm volatile(
            "mma.sync.aligned.m16n8k16.row.col.f32.bf16.bf16.f32 "
            "{%0,%1,%2,%3},{%4,%5,%6,%7},{%8,%9},{%0,%1,%2,%3};\n"
            : "+f"(c[0]), "+f"(c[1]), "+f"(c[2]), "+f"(c[3])
            : "r"(a[0]), "r"(a[1]), "r"(a[2]), "r"(a[3]), "r"(b0), "r"(b1));
    }
}

// ---------------------------------------------------------------------------
// Fused gate/up GEMM + SwiGLU (R10-proven config): 256 threads, 8 warps
// (4m x 2n), warp 32x64, block tile 128x128x64, double-buffered cp.async.
// 4 B matrices (Ghi,Glo,Uhi,Ulo) share the A tile; hi/lo share accumulators.
// inter = silu(xs*gate) * (xs*up), fp32 out.
// ---------------------------------------------------------------------------
__global__ void __launch_bounds__(256, 1)
fused_gateup_kernel(const uint16_t* __restrict__ A,
                    const uint16_t* __restrict__ Gh,
                    const uint16_t* __restrict__ Gl,
                    const uint16_t* __restrict__ Uh,
                    const uint16_t* __restrict__ Ul,
                    const float* __restrict__ rowscale,
                    float* __restrict__ Cout,
                    int K, int N)
{
    constexpr int TILE  = 16384;       // 128 rows * 128B
    constexpr int STAGE = 5 * TILE;    // A + 4 B tiles = 80KB

    extern __shared__ char smem_raw[];
    const uint32_t sb = (smem_u32(smem_raw) + 127u) & ~127u;

    const int tid  = threadIdx.x;
    const int warp = tid >> 5;
    const int lane = tid & 31;
    const int wm = warp & 3;          // 4 warps over M
    const int wn = warp >> 2;         // 2 warps over N
    const int bm = blockIdx.x * 128;
    const int bn = blockIdx.y * 128;

    const uint16_t* Bs[4] = {Gh, Gl, Uh, Ul};

    float acc[2][2][8][4];            // [gate/up][mi][ni][frag]
    #pragma unroll
    for (int q = 0; q < 2; q++)
        #pragma unroll
        for (int a = 0; a < 2; a++)
            #pragma unroll
            for (int b = 0; b < 8; b++)
                #pragma unroll
                for (int c = 0; c < 4; c++) acc[q][a][b][c] = 0.f;

    const int KT = K >> 6;   // BK=64

    // per-stage loader: 5 tiles x 1024 16B chunks, 256 threads -> 4 per tile
    auto load_stage = [&](int kt, int s) {
        const int k0 = kt * 64;
        #pragma unroll
        for (int i = 0; i < 4; i++) {
            int id  = tid + i * 256;       // 0..1023
            int row = id >> 3, c = id & 7;
            uint32_t dst = sb + s * STAGE + row * 128 + (((c ^ (row & 7)) << 4));
            cp_async16(dst, A + (size_t)(bm + row) * K + k0 + c * 8);
        }
        #pragma unroll
        for (int m = 0; m < 4; m++) {
            #pragma unroll
            for (int i = 0; i < 4; i++) {
                int id  = tid + i * 256;
                int row = id >> 3, c = id & 7;
                uint32_t dst = sb + s * STAGE + (1 + m) * TILE + row * 128
                             + (((c ^ (row & 7)) << 4));
                cp_async16(dst, Bs[m] + (size_t)(bn + row) * K + k0 + c * 8);
            }
        }
    };

    const int la7 = lane & 7;
    uint32_t a_row[2], b_row[4];
    #pragma unroll
    for (int mi = 0; mi < 2; mi++)
        a_row[mi] = (uint32_t)(wm * 32 + mi * 16 + la7 + ((lane >> 3) & 1) * 8) * 128;
    #pragma unroll
    for (int p = 0; p < 4; p++)
        b_row[p] = (uint32_t)(wn * 64 + p * 16 + la7 + (lane >> 4) * 8) * 128;
    const int kca = (lane >> 4);
    const int kcb = ((lane >> 3) & 1);

    load_stage(0, 0);
    cp_commit();

    for (int kt = 0; kt < KT; kt++) {
        cp_wait<0>();
        __syncthreads();
        if (kt + 1 < KT) load_stage(kt + 1, (kt + 1) & 1);
        cp_commit();

        const uint32_t base = sb + (kt & 1) * STAGE;
        #pragma unroll
        for (int kk = 0; kk < 4; kk++) {
            const uint32_t offa = (uint32_t)(((kk * 2 + kca) ^ la7) << 4);
            const uint32_t offb = (uint32_t)(((kk * 2 + kcb) ^ la7) << 4);
            uint32_t afr[2][4];
            ldsm_x4(afr[0], base + a_row[0] + offa);
            ldsm_x4(afr[1], base + a_row[1] + offa);
            #pragma unroll
            for (int p = 0; p < 4; p++) {
                #pragma unroll
                for (int m = 0; m < 4; m++) {
                    uint32_t bfr[4];
                    ldsm_x4(bfr, base + (1 + m) * TILE + b_row[p] + offb);
                    float* c0 = acc[m >> 1][0][2 * p];
                    float* c1 = acc[m >> 1][1][2 * p];
                    float* c2 = acc[m >> 1][0][2 * p + 1];
                    float* c3 = acc[m >> 1][1][2 * p + 1];
                    mma16816<false>(c0, afr[0], bfr[0], bfr[1]);
                    mma16816<false>(c1, afr[1], bfr[0], bfr[1]);
                    mma16816<false>(c2, afr[0], bfr[2], bfr[3]);
                    mma16816<false>(c3, afr[1], bfr[2], bfr[3]);
                }
            }
        }
    }

    // epilogue: inter = silu(xs*gate) * (xs*up)
    #pragma unroll
    for (int mi = 0; mi < 2; mi++) {
        const int r0 = bm + wm * 32 + mi * 16 + (lane >> 2);
        const float s0 = rowscale[r0];
        const float s1 = rowscale[r0 + 8];
        #pragma unroll
        for (int ni = 0; ni < 8; ni++) {
            const int col = bn + wn * 64 + ni * 8 + (lane & 3) * 2;
            float g0 = acc[0][mi][ni][0] * s0, g1 = acc[0][mi][ni][1] * s0;
            float u0 = acc[1][mi][ni][0] * s0, u1 = acc[1][mi][ni][1] * s0;
            float v0 = __fdividef(g0, 1.f + expf(-g0)) * u0;
            float v1 = __fdividef(g1, 1.f + expf(-g1)) * u1;
            *(float2*)&Cout[(size_t)r0 * N + col] = make_float2(v0, v1);
            float g2 = acc[0][mi][ni][2] * s1, g3 = acc[0][mi][ni][3] * s1;
            float u2 = acc[1][mi][ni][2] * s1, u3 = acc[1][mi][ni][3] * s1;
            float v2 = __fdividef(g2, 1.f + expf(-g2)) * u2;
            float v3 = __fdividef(g3, 1.f + expf(-g3)) * u3;
            *(float2*)&Cout[(size_t)(r0 + 8) * N + col] = make_float2(v2, v3);
        }
    }
}

// ---------------------------------------------------------------------------
// Down GEMM (fp16 single), 256 threads, 8 warps (4m x 2n), warp 32x64,
// BM=128 BN=128 BK=64, 2-stage double buffer (R10-proven), 2 CTAs/SM.
// ---------------------------------------------------------------------------
__global__ void __launch_bounds__(256, 2)
down_gemm_kernel(const uint16_t* __restrict__ A,
                 const uint16_t* __restrict__ B0,
                 const float* __restrict__ rowscale,
                 float* __restrict__ Cout,
                 int K, int N)
{
    constexpr int TILE  = 16384;
    constexpr int STAGE = 2 * TILE;     // A + B = 32KB

    extern __shared__ char smem_raw[];
    const uint32_t sb = (smem_u32(smem_raw) + 127u) & ~127u;

    const int tid  = threadIdx.x;
    const int warp = tid >> 5;
    const int lane = tid & 31;
    const int wm = warp & 3;
    const int wn = warp >> 2;
    const int bm = blockIdx.x * 128;
    const int bn = blockIdx.y * 128;

    float acc[2][8][4];
    #pragma unroll
    for (int a = 0; a < 2; a++)
        #pragma unroll
        for (int b = 0; b < 8; b++)
            #pragma unroll
            for (int c = 0; c < 4; c++) acc[a][b][c] = 0.f;

    const int KT = K >> 6;

    auto load_stage = [&](int kt, int s) {
        const int k0 = kt * 64;
        #pragma unroll
        for (int i = 0; i < 4; i++) {
            int id  = tid + i * 256;
            int row = id >> 3, c = id & 7;
            uint32_t doff = (uint32_t)(row * 128 + (((c ^ (row & 7)) << 4)));
            cp_async16(sb + s * STAGE + doff,        A  + (size_t)(bm + row) * K + k0 + c * 8);
            cp_async16(sb + s * STAGE + TILE + doff, B0 + (size_t)(bn + row) * K + k0 + c * 8);
        }
    };

    const int la7 = lane & 7;
    uint32_t a_row[2], b_row[4];
    #pragma unroll
    for (int mi = 0; mi < 2; mi++)
        a_row[mi] = (uint32_t)(wm * 32 + mi * 16 + la7 + ((lane >> 3) & 1) * 8) * 128;
    #pragma unroll
    for (int p = 0; p < 4; p++)
        b_row[p] = (uint32_t)(wn * 64 + p * 16 + la7 + (lane >> 4) * 8) * 128;
    const int kca = (lane >> 4);
    const int kcb = ((lane >> 3) & 1);

    load_stage(0, 0);
    cp_commit();

    for (int kt = 0; kt < KT; kt++) {
        cp_wait<0>();
        __syncthreads();
        if (kt + 1 < KT) load_stage(kt + 1, (kt + 1) & 1);
        cp_commit();

        const uint32_t base = sb + (kt & 1) * STAGE;
        #pragma unroll
        for (int kk = 0; kk < 4; kk++) {
            const uint32_t offa = (uint32_t)(((kk * 2 + kca) ^ la7) << 4);
            const uint32_t offb = (uint32_t)(((kk * 2 + kcb) ^ la7) << 4);
            uint32_t afr[2][4];
            ldsm_x4(afr[0], base + a_row[0] + offa);
            ldsm_x4(afr[1], base + a_row[1] + offa);
            #pragma unroll
            for (int p = 0; p < 4; p++) {
                uint32_t bfr[4];
                ldsm_x4(bfr, base + TILE + b_row[p] + offb);
                mma16816<true>(acc[0][2 * p],     afr[0], bfr[0], bfr[1]);
                mma16816<true>(acc[1][2 * p],     afr[1], bfr[0], bfr[1]);
                mma16816<true>(acc[0][2 * p + 1], afr[0], bfr[2], bfr[3]);
                mma16816<true>(acc[1][2 * p + 1], afr[1], bfr[2], bfr[3]);
            }
        }
    }

    #pragma unroll
    for (int mi = 0; mi < 2; mi++) {
        const int r0 = bm + wm * 32 + mi * 16 + (lane >> 2);
        const float s0 = rowscale[r0];
        const float s1 = rowscale[r0 + 8];
        #pragma unroll
        for (int ni = 0; ni < 8; ni++) {
            const int col = bn + wn * 64 + ni * 8 + (lane & 3) * 2;
            *(float2*)&Cout[(size_t)r0 * N + col] =
                make_float2(acc[mi][ni][0] * s0, acc[mi][ni][1] * s0);
            *(float2*)&Cout[(size_t)(r0 + 8) * N + col] =
                make_float2(acc[mi][ni][2] * s1, acc[mi][ni][3] * s1);
        }
    }
}

// ---------------------------------------------------------------------------
// Weight split fp32 -> bf16 hi/lo: 8 floats/thread, 16B stores, streaming.
// ---------------------------------------------------------------------------
struct alignas(16) BF8 { __nv_bfloat162 a, b, c, d; };

__global__ void split_one_kernel(const float4* __restrict__ src,
                                 BF8* __restrict__ hi,
                                 BF8* __restrict__ lo, int n8) {
    const int stride = gridDim.x * blockDim.x;
    for (int i = blockIdx.x * blockDim.x + threadIdx.x; i < n8; i += stride) {
        float4 w0 = __ldcs(&src[2 * i]);
        float4 w1 = __ldcs(&src[2 * i + 1]);
        BF8 h, l;
        __nv_bfloat16 h0 = __float2bfloat16_rn(w0.x), h1 = __float2bfloat16_rn(w0.y);
        __nv_bfloat16 h2 = __float2bfloat16_rn(w0.z), h3 = __float2bfloat16_rn(w0.w);
        __nv_bfloat16 h4 = __float2bfloat16_rn(w1.x), h5 = __float2bfloat16_rn(w1.y);
        __nv_bfloat16 h6 = __float2bfloat16_rn(w1.z), h7 = __float2bfloat16_rn(w1.w);
        h.a = __halves2bfloat162(h0, h1);  h.b = __halves2bfloat162(h2, h3);
        h.c = __halves2bfloat162(h4, h5);  h.d = __halves2bfloat162(h6, h7);
        l.a = __halves2bfloat162(__float2bfloat16_rn(w0.x - __bfloat162float(h0)),
                                 __float2bfloat16_rn(w0.y - __bfloat162float(h1)));
        l.b = __halves2bfloat162(__float2bfloat16_rn(w0.z - __bfloat162float(h2)),
                                 __float2bfloat16_rn(w0.w - __bfloat162float(h3)));
        l.c = __halves2bfloat162(__float2bfloat16_rn(w1.x - __bfloat162float(h4)),
                                 __float2bfloat16_rn(w1.y - __bfloat162float(h5)));
        l.d = __halves2bfloat162(__float2bfloat16_rn(w1.z - __bfloat162float(h6)),
                                 __float2bfloat16_rn(w1.w - __bfloat162float(h7)));
        __stcs((float4*)&hi[i], *(float4*)&h);
        __stcs((float4*)&lo[i], *(float4*)&l);
    }
}

// ---------------------------------------------------------------------------
// fp32 -> fp16 convert (down weights): 8 floats/thread, 16B stores, streaming
// ---------------------------------------------------------------------------
struct alignas(16) H8 { __half2 a, b, c, d; };

__global__ void conv_half_kernel(const float4* __restrict__ src,
                                 H8* __restrict__ dst, int n8) {
    const int stride = gridDim.x * blockDim.x;
    for (int i = blockIdx.x * blockDim.x + threadIdx.x; i < n8; i += stride) {
        float4 w0 = __ldcs(&src[2 * i]);
        float4 w1 = __ldcs(&src[2 * i + 1]);
        H8 h;
        h.a = __floats2half2_rn(w0.x, w0.y);
        h.b = __floats2half2_rn(w0.z, w0.w);
        h.c = __floats2half2_rn(w1.x, w1.y);
        h.d = __floats2half2_rn(w1.z, w1.w);
        __stcs((float4*)&dst[i], *(float4*)&h);
    }
}

// ---------------------------------------------------------------------------
// Block max-reduce
// ---------------------------------------------------------------------------
__device__ __forceinline__ float block_max(float v, float* red) {
    #pragma unroll
    for (int o = 16; o; o >>= 1) v = fmaxf(v, __shfl_xor_sync(0xFFFFFFFFu, v, o));
    if ((threadIdx.x & 31) == 0) red[threadIdx.x >> 5] = v;
    __syncthreads();
    if (threadIdx.x < 32) {
        float w = (threadIdx.x < (blockDim.x >> 5)) ? red[threadIdx.x] : 0.f;
        #pragma unroll
        for (int o = 16; o; o >>= 1) w = fmaxf(w, __shfl_xor_sync(0xFFFFFFFFu, w, o));
        if (threadIdx.x == 0) red[0] = w;
    }
    __syncthreads();
    return red[0];
}

// ---------------------------------------------------------------------------
// Per-token fake-quant of x -> bf16 ints (row cached in smem)
// ---------------------------------------------------------------------------
__global__ void quant_x_kernel(const float* __restrict__ x) {
    __shared__ float red[32];
    __shared__ float row[HDIM];
    const int t = blockIdx.x;
    const float4* xr = (const float4*)(x + (size_t)t * HDIM);
    float amax = 0.f;
    for (int i = threadIdx.x; i < HDIM / 4; i += blockDim.x) {
        float4 v = xr[i];
        ((float4*)row)[i] = v;
        amax = fmaxf(amax, fmaxf(fmaxf(fabsf(v.x), fabsf(v.y)), fmaxf(fabsf(v.z), fabsf(v.w))));
    }
    __syncthreads();
    amax = block_max(amax, red);
    const float scale = fmaxf(amax * (1.0f / 127.0f), 1e-8f);
    if (threadIdx.x == 0) g_xscale[t] = scale;
    const float inv = 1.0f / scale;
    for (int i = threadIdx.x; i < HDIM; i += blockDim.x) {
        float q = rintf(row[i] * inv);
        q = fminf(fmaxf(q, -128.f), 127.f);
        g_xq[(size_t)t * HDIM + i] = __float2bfloat16_rn(q);
    }
}

// ---------------------------------------------------------------------------
// Per-token fake-quant of inter -> fp16 ints
// ---------------------------------------------------------------------------
__global__ void quant2_kernel() {
    extern __shared__ float srow[];    // IDIM floats
    __shared__ float red[32];
    const int t = blockIdx.x;
    const float4* ir = (const float4*)(g_inter + (size_t)t * IDIM);
    float amax = 0.f;
    for (int i = threadIdx.x; i < IDIM / 4; i += blockDim.x) {
        float4 v = ir[i];
        ((float4*)srow)[i] = v;
        amax = fmaxf(amax, fmaxf(fmaxf(fabsf(v.x), fabsf(v.y)), fmaxf(fabsf(v.z), fabsf(v.w))));
    }
    __syncthreads();
    amax = block_max(amax, red);
    const float scale = fmaxf(amax * (1.0f / 127.0f), 1e-8f);
    if (threadIdx.x == 0) g_s2[t] = scale;
    const float inv = 1.0f / scale;
    for (int i = threadIdx.x; i < IDIM; i += blockDim.x) {
        float q = rintf(srow[i] * inv);
        q = fminf(fmaxf(q, -128.f), 127.f);
        g_q2h[(size_t)t * IDIM + i] = __float2half_rn(q);
    }
}

// ---------------------------------------------------------------------------
// Host launcher
// ---------------------------------------------------------------------------
extern "C" void kernel_launch(void* const* d_in, const int* in_sizes, int n_in,
                              void* d_out, int out_size) {
    const float* x  = (const float*)d_in[0];
    const float* wg = (const float*)d_in[1];
    const float* wu = (const float*)d_in[2];
    const float* wd = (const float*)d_in[3];
    float* out = (float*)d_out;
    (void)in_sizes; (void)n_in; (void)out_size;

    void *p_xq, *p_xs, *p_inter, *p_q2, *p_s2;
    void *p_wgh, *p_wgl, *p_wuh, *p_wul, *p_wdh;
    cudaGetSymbolAddress(&p_xq, g_xq);      cudaGetSymbolAddress(&p_xs, g_xscale);
    cudaGetSymbolAddress(&p_inter, g_inter);
    cudaGetSymbolAddress(&p_q2, g_q2h);     cudaGetSymbolAddress(&p_s2, g_s2);
    cudaGetSymbolAddress(&p_wgh, g_wg_hi);  cudaGetSymbolAddress(&p_wgl, g_wg_lo);
    cudaGetSymbolAddress(&p_wuh, g_wu_hi);  cudaGetSymbolAddress(&p_wul, g_wu_lo);
    cudaGetSymbolAddress(&p_wdh, g_wd_h);

    const int smem_fused = 2 * 5 * 16384 + 128;   // 163968
    const int smem_down  = 2 * 2 * 16384 + 128;   // 65664
    const int smem_q2    = IDIM * (int)sizeof(float);
    cudaFuncSetAttribute(fused_gateup_kernel,
                         cudaFuncAttributeMaxDynamicSharedMemorySize, smem_fused);
    cudaFuncSetAttribute(down_gemm_kernel,
                         cudaFuncAttributeMaxDynamicSharedMemorySize, smem_down);
    cudaFuncSetAttribute(quant2_kernel,
                         cudaFuncAttributeMaxDynamicSharedMemorySize, smem_q2);

    // 1) gate/up weights -> bf16 hi/lo; down weights -> fp16 (streaming)
    const int n8 = (IDIM / 8) * HDIM;   // 8-float groups
    split_one_kernel<<<2048, 256>>>((const float4*)wg, (BF8*)p_wgh, (BF8*)p_wgl, n8);
    split_one_kernel<<<2048, 256>>>((const float4*)wu, (BF8*)p_wuh, (BF8*)p_wul, n8);
    conv_half_kernel<<<2048, 256>>>((const float4*)wd, (H8*)p_wdh, n8);

    // 2) per-token fake-quant of x
    quant_x_kernel<<<M_TOK, 256>>>(x);

    // 3) fused gate/up GEMM (bf16 hi+lo) + SwiGLU epilogue -> inter
    dim3 g1(M_TOK / 128, IDIM / 128);   // (32, 112), m fastest
    fused_gateup_kernel<<<g1, 256, smem_fused>>>(
        (const uint16_t*)p_xq,
        (const uint16_t*)p_wgh, (const uint16_t*)p_wgl,
        (const uint16_t*)p_wuh, (const uint16_t*)p_wul,
        (const float*)p_xs, (float*)p_inter, HDIM, IDIM);

    // 4) fake-quant of inter -> fp16 ints
    quant2_kernel<<<M_TOK, 512, smem_q2>>>();

    // 5) down GEMM (fp16 single) -> out
    dim3 g3(M_TOK / 128, HDIM / 128);   // (32, 32)
    down_gemm_kernel<<<g3, 256, smem_down>>>(
        (const uint16_t*)p_q2, (const uint16_t*)p_wdh,
        (const float*)p_s2, out, IDIM, HDIM);
}